// round 1
// baseline (speedup 1.0000x reference)
#include <cuda_runtime.h>
#include <cuda_bf16.h>

// Leapfrog (kick-drift-kick) integrator, GM = 1, A_SCALE = 1.
// One thread per (particle, stream) pair. tid = 2*i + s where s=0 -> trail,
// s=1 -> lead; that is exactly the output row index after the reference's
// stack([trail, lead], axis=1).reshape(2N, 6), so stores are contiguous.

__device__ __forceinline__ float rsqrt_approx(float x) {
    float y;
    asm("rsqrt.approx.f32 %0, %1;" : "=f"(y) : "f"(x));
    return y;
}

__device__ __forceinline__ float rcp_approx(float x) {
    float y;
    asm("rcp.approx.f32 %0, %1;" : "=f"(y) : "f"(x));
    return y;
}

// a = -q / (r*(r+1)^2 + 1e-12), r = |q|
__device__ __forceinline__ void accel(float qx, float qy, float qz,
                                      float& ax, float& ay, float& az) {
    // 1e-30 seed keeps s>0 so rsqrt stays finite; r = s*rsqrt(s) = sqrt(s),
    // and at s==0 we get r=0 -> den=1e-12, matching the reference guard.
    float s = fmaf(qx, qx, fmaf(qy, qy, fmaf(qz, qz, 1e-30f)));
    float u = rsqrt_approx(s);          // 1/sqrt(s)   (MUFU)
    float r = s * u;                    // sqrt(s)
    float rp1 = r + 1.0f;
    float den = fmaf(r * rp1, rp1, 1e-12f);
    float f = rcp_approx(den);          // 1/den       (MUFU)
    f = -f;                             // GM = 1
    ax = qx * f;
    ay = qy * f;
    az = qz * f;
}

struct State {
    float qx, qy, qz, px, py, pz, ax, ay, az;
};

__device__ __forceinline__ void step(State& st, float dt, float hdt) {
    // p_half = p + 0.5*dt*a       (a == accel(q) carried from previous step)
    st.px = fmaf(hdt, st.ax, st.px);
    st.py = fmaf(hdt, st.ay, st.py);
    st.pz = fmaf(hdt, st.az, st.pz);
    // q_new = q + dt*p_half
    st.qx = fmaf(dt, st.px, st.qx);
    st.qy = fmaf(dt, st.py, st.qy);
    st.qz = fmaf(dt, st.pz, st.qz);
    // a = accel(q_new)
    accel(st.qx, st.qy, st.qz, st.ax, st.ay, st.az);
    // p_new = p_half + 0.5*dt*a
    st.px = fmaf(hdt, st.ax, st.px);
    st.py = fmaf(hdt, st.ay, st.py);
    st.pz = fmaf(hdt, st.az, st.pz);
}

__global__ void __launch_bounds__(256)
stream_integrate_kernel(const float* __restrict__ ts,
                        const float* __restrict__ w_lead,
                        const float* __restrict__ w_trail,
                        const int*   __restrict__ n_steps_p,
                        float* __restrict__ out,
                        int n) {
    int tid = blockIdx.x * blockDim.x + threadIdx.x;
    if (tid >= 2 * n) return;

    int i = tid >> 1;       // particle index
    int s = tid & 1;        // 0 = trail, 1 = lead
    const float* w0 = s ? w_lead : w_trail;

    // Row i*6 floats = 24*i bytes -> 8-byte aligned: load as 3x float2.
    const float2* src = reinterpret_cast<const float2*>(w0 + (size_t)i * 6);
    float2 v0 = src[0];
    float2 v1 = src[1];
    float2 v2 = src[2];

    State st;
    st.qx = v0.x; st.qy = v0.y; st.qz = v1.x;
    st.px = v1.y; st.py = v2.x; st.pz = v2.y;

    float t_f = ts[n - 1] + 0.001f;       // broadcast, L2-cached
    int   nst = *n_steps_p;
    float dt  = (t_f - ts[i]) / (float)nst;
    float hdt = 0.5f * dt;

    // Prime the carried acceleration: accel(q0).
    accel(st.qx, st.qy, st.qz, st.ax, st.ay, st.az);

    if (nst == 64) {
        #pragma unroll 8
        for (int k = 0; k < 64; ++k) step(st, dt, hdt);
    } else {
        for (int k = 0; k < nst; ++k) step(st, dt, hdt);
    }

    float2* dst = reinterpret_cast<float2*>(out + (size_t)tid * 6);
    dst[0] = make_float2(st.qx, st.qy);
    dst[1] = make_float2(st.qz, st.px);
    dst[2] = make_float2(st.py, st.pz);
}

extern "C" void kernel_launch(void* const* d_in, const int* in_sizes, int n_in,
                              void* d_out, int out_size) {
    const float* ts      = (const float*)d_in[0];
    const float* w_lead  = (const float*)d_in[1];
    const float* w_trail = (const float*)d_in[2];
    const int*   n_steps = (const int*)d_in[3];
    float*       out     = (float*)d_out;

    int n = in_sizes[0];                 // 65536 particles
    int total = 2 * n;                   // one thread per (particle, stream)
    int block = 256;
    int grid = (total + block - 1) / block;
    stream_integrate_kernel<<<grid, block>>>(ts, w_lead, w_trail, n_steps, out, n);
}